// round 4
// baseline (speedup 1.0000x reference)
#include <cuda_runtime.h>
#include <cuda_fp16.h>
#include <cstdint>

// Problem dims
#define BT_TOK 16384   // B*T
#define F_DIM  64
#define H_DIM  8
#define E_DIM  64
#define P_DIM  512
#define K_DIM  1024    // 2 * F * H  (x-branch cols 0..511, time-branch 512..1023)

// -------- device scratch (static globals; no allocation allowed) --------
__device__ __half g_Hhi[(size_t)BT_TOK * K_DIM];
__device__ __half g_Hlo[(size_t)BT_TOK * K_DIM];
__device__ __half g_Whi[(size_t)P_DIM * K_DIM];   // [p][k]  K-contiguous (col-major B)
__device__ __half g_Wlo[(size_t)P_DIM * K_DIM];
__device__ float  g_bias[P_DIM];

// -------- helpers --------
__device__ __forceinline__ uint32_t smem_u32(const void* p) {
    uint32_t a;
    asm("{ .reg .u64 t; cvta.to.shared.u64 t, %1; cvt.u32.u64 %0, t; }" : "=r"(a) : "l"(p));
    return a;
}
__device__ __forceinline__ void cp_async16(uint32_t dst, const void* src) {
    asm volatile("cp.async.cg.shared.global [%0], [%1], 16;" :: "r"(dst), "l"(src));
}
__device__ __forceinline__ void ldmatrix_x4(uint32_t r[4], uint32_t addr) {
    asm volatile("ldmatrix.sync.aligned.m8n8.x4.shared.b16 {%0,%1,%2,%3}, [%4];"
                 : "=r"(r[0]), "=r"(r[1]), "=r"(r[2]), "=r"(r[3]) : "r"(addr));
}
__device__ __forceinline__ void mma16816(float c[4], const uint32_t a[4],
                                         uint32_t b0, uint32_t b1) {
    asm volatile(
        "mma.sync.aligned.m16n8k16.row.col.f32.f16.f16.f32 "
        "{%0,%1,%2,%3}, {%4,%5,%6,%7}, {%8,%9}, {%0,%1,%2,%3};"
        : "+f"(c[0]), "+f"(c[1]), "+f"(c[2]), "+f"(c[3])
        : "r"(a[0]), "r"(a[1]), "r"(a[2]), "r"(a[3]), "r"(b0), "r"(b1));
}
__device__ __forceinline__ void split_h(float v, __half& hi, __half& lo) {
    hi = __float2half_rn(v);
    lo = __float2half_rn(v - __half2float(hi));
}

// ============================================================================
// Kernel 1: bias fold
// ============================================================================
__global__ void bias_kernel(const float* __restrict__ bx, const float* __restrict__ bt) {
    int p = threadIdx.x;
    g_bias[p] = bx[p] + bt[p];
}

// ============================================================================
// Kernel 2: weight pre-contraction
//   Wc[f*H+h, p]     = sum_e w2v[f,h,e] * wx[f*E+e, p]
//   Wc[512+f*H+h, p] = sum_e w2t[f,h,e] * wt[f*E+e, p]
// stored transposed + fp16 hi/lo:  g_Whi/g_Wlo [p][k]
// ============================================================================
__global__ void __launch_bounds__(128) precompute_kernel(
    const float* __restrict__ w2v, const float* __restrict__ w2t,
    const float* __restrict__ wx,  const float* __restrict__ wt) {
    int f  = blockIdx.y;
    int br = blockIdx.z;
    int p  = blockIdx.x * 128 + threadIdx.x;
    const float* w2 = br ? w2t : w2v;
    const float* w  = br ? wt  : wx;

    __shared__ float s_w2[H_DIM][E_DIM];
    for (int idx = threadIdx.x; idx < H_DIM * E_DIM; idx += 128)
        s_w2[idx >> 6][idx & 63] = w2[f * H_DIM * E_DIM + idx];
    __syncthreads();

    float acc[H_DIM];
#pragma unroll
    for (int h = 0; h < H_DIM; h++) acc[h] = 0.0f;

    const float* wcol = w + (size_t)f * E_DIM * P_DIM + p;
#pragma unroll 4
    for (int e = 0; e < E_DIM; e++) {
        float wv = wcol[(size_t)e * P_DIM];
#pragma unroll
        for (int h = 0; h < H_DIM; h++) acc[h] = fmaf(s_w2[h][e], wv, acc[h]);
    }

    int kb = br * 512 + f * 8;
    union { uint4 u; __half2 h2[4]; } Hv, Lv;
#pragma unroll
    for (int h2 = 0; h2 < 4; h2++) {
        __half h0, l0, h1, l1;
        split_h(acc[2 * h2 + 0], h0, l0);
        split_h(acc[2 * h2 + 1], h1, l1);
        Hv.h2[h2] = __halves2half2(h0, h1);
        Lv.h2[h2] = __halves2half2(l0, l1);
    }
    *reinterpret_cast<uint4*>(&g_Whi[(size_t)p * K_DIM + kb]) = Hv.u;
    *reinterpret_cast<uint4*>(&g_Wlo[(size_t)p * K_DIM + kb]) = Lv.u;
}

// ============================================================================
// Kernel 3: activations  H[i, f*8+h] = tanh(x[i,f]*w1[f,h] + b1[f,h])
//   fp16 hi/lo split into g_Hhi/g_Hlo [i][k]; one thread per (token,feature)
// ============================================================================
__global__ void __launch_bounds__(256) act_kernel(
    const float* __restrict__ x,   const float* __restrict__ tmv,
    const float* __restrict__ w1v, const float* __restrict__ b1v,
    const float* __restrict__ w1t, const float* __restrict__ b1t) {
    int idx = blockIdx.x * 256 + threadIdx.x;     // < BT_TOK * F_DIM
    int i = idx >> 6, f = idx & 63;
    float xv = x[idx], tv = tmv[idx];

    union { uint4 u; __half2 h2[4]; } XH, XL, TH, TL;
#pragma unroll
    for (int h2 = 0; h2 < 4; h2++) {
        int w0 = f * 8 + 2 * h2, w1 = w0 + 1;
        float a0 = tanhf(fmaf(xv, w1v[w0], b1v[w0]));
        float a1 = tanhf(fmaf(xv, w1v[w1], b1v[w1]));
        float c0 = tanhf(fmaf(tv, w1t[w0], b1t[w0]));
        float c1 = tanhf(fmaf(tv, w1t[w1], b1t[w1]));
        __half h0, l0, h1, l1;
        split_h(a0, h0, l0); split_h(a1, h1, l1);
        XH.h2[h2] = __halves2half2(h0, h1);
        XL.h2[h2] = __halves2half2(l0, l1);
        split_h(c0, h0, l0); split_h(c1, h1, l1);
        TH.h2[h2] = __halves2half2(h0, h1);
        TL.h2[h2] = __halves2half2(l0, l1);
    }
    size_t ox = (size_t)i * K_DIM + f * 8;
    size_t ot = ox + 512;
    *reinterpret_cast<uint4*>(&g_Hhi[ox]) = XH.u;
    *reinterpret_cast<uint4*>(&g_Hlo[ox]) = XL.u;
    *reinterpret_cast<uint4*>(&g_Hhi[ot]) = TH.u;
    *reinterpret_cast<uint4*>(&g_Hlo[ot]) = TL.u;
}

// ============================================================================
// Kernel 4: GEMM  out[16384,512] = H @ Wc^T + bias  via mma.sync (HMMA)
//   split precision: D = Ahi*Bhi + Alo*Bhi + Ahi*Blo  (fp32 accum)
//   CTA 128x256, 512 threads, warp tile 32x64, Kc=64, double-buffered cp.async
// ============================================================================
#define CTA_M   128
#define CTA_N   256
#define KC      64
#define A_STAGE (CTA_M * KC * 2)            // 16 KB
#define B_STAGE (CTA_N * KC * 2)            // 32 KB
#define STAGE   (A_STAGE + B_STAGE)         // 48 KB
#define SMEM_GEMM (2 * STAGE)               // 96 KB
#define N_ITERS 48                          // 3 passes * 16 K-chunks

__global__ void __launch_bounds__(512, 1) gemm_kernel(float* __restrict__ out) {
    extern __shared__ char smem[];
    const int tid  = threadIdx.x;
    const int lane = tid & 31;
    const int wid  = tid >> 5;
    const int wm   = (wid & 3) * 32;     // warp M offset in CTA tile
    const int wn   = (wid >> 2) * 64;    // warp N offset
    const int m0   = blockIdx.x * CTA_M;
    const int n0   = blockIdx.y * CTA_N;
    const uint32_t sb = smem_u32(smem);

    float acc[2][8][4];
#pragma unroll
    for (int im = 0; im < 2; im++)
#pragma unroll
        for (int in = 0; in < 8; in++)
#pragma unroll
            for (int q = 0; q < 4; q++) acc[im][in][q] = 0.0f;

    // ldmatrix per-lane row/col decomposition
    const int arow = (lane & 7) + ((lane >> 3) & 1) * 8;   // + wm + im*16
    const int acb  = (lane >> 4) & 1;                      // k+8 selector
    const int brow = (lane & 7) + ((lane >> 4) & 1) * 8;   // + wn + j*16
    const int bcb  = (lane >> 3) & 1;

    // stage loader: it -> (pass, kchunk)
    auto load_stage = [&](int it) {
        int p  = it >> 4;
        int kc = it & 15;
        const __half* A = (p == 1) ? g_Hlo : g_Hhi;
        const __half* B = (p == 2) ? g_Wlo : g_Whi;
        A += (size_t)m0 * K_DIM + kc * KC;
        B += (size_t)n0 * K_DIM + kc * KC;
        uint32_t base = sb + (uint32_t)(it & 1) * STAGE;
#pragma unroll
        for (int t = 0; t < 2; t++) {            // A: 1024 x 16B
            int u = tid + t * 512;
            int row = u >> 3, c = u & 7;
            uint32_t so = base + row * 128 + ((c ^ (row & 7)) << 4);
            cp_async16(so, (const char*)(A + (size_t)row * K_DIM) + c * 16);
        }
        uint32_t bb = base + A_STAGE;
#pragma unroll
        for (int t = 0; t < 4; t++) {            // B: 2048 x 16B
            int u = tid + t * 512;
            int row = u >> 3, c = u & 7;
            uint32_t so = bb + row * 128 + ((c ^ (row & 7)) << 4);
            cp_async16(so, (const char*)(B + (size_t)row * K_DIM) + c * 16);
        }
        asm volatile("cp.async.commit_group;" ::: "memory");
    };

    load_stage(0);

    for (int it = 0; it < N_ITERS; it++) {
        asm volatile("cp.async.wait_group 0;" ::: "memory");
        __syncthreads();
        if (it + 1 < N_ITERS) load_stage(it + 1);

        uint32_t abase = sb + (uint32_t)(it & 1) * STAGE;
        uint32_t bbase = abase + A_STAGE;
#pragma unroll
        for (int ks = 0; ks < 4; ks++) {
            uint32_t a[2][4];
#pragma unroll
            for (int im = 0; im < 2; im++) {
                int row = wm + arow + im * 16;
                int c = ks * 2 + acb;
                ldmatrix_x4(a[im], abase + row * 128 + ((c ^ (row & 7)) << 4));
            }
            uint32_t b[4][4];
#pragma unroll
            for (int j = 0; j < 4; j++) {
                int row = wn + brow + j * 16;
                int c = ks * 2 + bcb;
                ldmatrix_x4(b[j], bbase + row * 128 + ((c ^ (row & 7)) << 4));
            }
#pragma unroll
            for (int im = 0; im < 2; im++)
#pragma unroll
                for (int j = 0; j < 4; j++) {
                    mma16816(acc[im][2 * j],     a[im], b[j][0], b[j][1]);
                    mma16816(acc[im][2 * j + 1], a[im], b[j][2], b[j][3]);
                }
        }
    }

    // epilogue: add bias, write fp32
#pragma unroll
    for (int im = 0; im < 2; im++) {
        int r0 = m0 + wm + im * 16 + (lane >> 2);
#pragma unroll
        for (int in = 0; in < 8; in++) {
            int cidx = n0 + wn + in * 8 + (lane & 3) * 2;
            float b0 = g_bias[cidx], b1 = g_bias[cidx + 1];
            float2 v0 = make_float2(acc[im][in][0] + b0, acc[im][in][1] + b1);
            float2 v1 = make_float2(acc[im][in][2] + b0, acc[im][in][3] + b1);
            *reinterpret_cast<float2*>(out + (size_t)r0 * P_DIM + cidx) = v0;
            *reinterpret_cast<float2*>(out + (size_t)(r0 + 8) * P_DIM + cidx) = v1;
        }
    }
}

// ============================================================================
extern "C" void kernel_launch(void* const* d_in, const int* in_sizes, int n_in,
                              void* d_out, int out_size) {
    const float* x   = (const float*)d_in[0];
    const float* tmv = (const float*)d_in[1];
    const float* w1v = (const float*)d_in[2];
    const float* b1v = (const float*)d_in[3];
    const float* w2v = (const float*)d_in[4];
    const float* w1t = (const float*)d_in[5];
    const float* b1t = (const float*)d_in[6];
    const float* w2t = (const float*)d_in[7];
    const float* wx  = (const float*)d_in[8];
    const float* bx  = (const float*)d_in[9];
    const float* wt  = (const float*)d_in[10];
    const float* bt  = (const float*)d_in[11];
    float* out = (float*)d_out;

    bias_kernel<<<1, 512>>>(bx, bt);
    precompute_kernel<<<dim3(4, 64, 2), 128>>>(w2v, w2t, wx, wt);
    act_kernel<<<(BT_TOK * F_DIM) / 256, 256>>>(x, tmv, w1v, b1v, w1t, b1t);

    cudaFuncSetAttribute(gemm_kernel, cudaFuncAttributeMaxDynamicSharedMemorySize, SMEM_GEMM);
    gemm_kernel<<<dim3(BT_TOK / CTA_M, P_DIM / CTA_N), 512, SMEM_GEMM>>>(out);
}

// round 8
// speedup vs baseline: 1.3005x; 1.3005x over previous
#include <cuda_runtime.h>
#include <cuda_fp16.h>
#include <cstdint>

// Problem dims
#define BT_TOK 16384   // B*T
#define F_DIM  64
#define H_DIM  8
#define E_DIM  64
#define P_DIM  512
#define K_DIM  1024    // 2 * F * H  (x-branch cols 0..511, time-branch 512..1023)

// -------- device scratch (static globals; no allocation allowed) --------
__device__ __half g_Hhi[(size_t)BT_TOK * K_DIM];
__device__ __half g_Hlo[(size_t)BT_TOK * K_DIM];
__device__ __half g_Whi[(size_t)P_DIM * K_DIM];   // [p][k]  K-contiguous (col-major B)
__device__ __half g_Wlo[(size_t)P_DIM * K_DIM];   // kept for possible 3-pass fallback
__device__ float  g_bias[P_DIM];

// -------- helpers --------
__device__ __forceinline__ uint32_t smem_u32(const void* p) {
    uint32_t a;
    asm("{ .reg .u64 t; cvta.to.shared.u64 t, %1; cvt.u32.u64 %0, t; }" : "=r"(a) : "l"(p));
    return a;
}
__device__ __forceinline__ void cp_async16(uint32_t dst, const void* src) {
    asm volatile("cp.async.cg.shared.global [%0], [%1], 16;" :: "r"(dst), "l"(src));
}
__device__ __forceinline__ void ldmatrix_x4(uint32_t r[4], uint32_t addr) {
    asm volatile("ldmatrix.sync.aligned.m8n8.x4.shared.b16 {%0,%1,%2,%3}, [%4];"
                 : "=r"(r[0]), "=r"(r[1]), "=r"(r[2]), "=r"(r[3]) : "r"(addr));
}
__device__ __forceinline__ void mma16816(float c[4], const uint32_t a[4],
                                         uint32_t b0, uint32_t b1) {
    asm volatile(
        "mma.sync.aligned.m16n8k16.row.col.f32.f16.f16.f32 "
        "{%0,%1,%2,%3}, {%4,%5,%6,%7}, {%8,%9}, {%0,%1,%2,%3};"
        : "+f"(c[0]), "+f"(c[1]), "+f"(c[2]), "+f"(c[3])
        : "r"(a[0]), "r"(a[1]), "r"(a[2]), "r"(a[3]), "r"(b0), "r"(b1));
}
__device__ __forceinline__ void split_h(float v, __half& hi, __half& lo) {
    hi = __float2half_rn(v);
    lo = __float2half_rn(v - __half2float(hi));
}

// ============================================================================
// Kernel 1: bias fold
// ============================================================================
__global__ void bias_kernel(const float* __restrict__ bx, const float* __restrict__ bt) {
    int p = threadIdx.x;
    g_bias[p] = bx[p] + bt[p];
}

// ============================================================================
// Kernel 2: weight pre-contraction
//   Wc[f*H+h, p]     = sum_e w2v[f,h,e] * wx[f*E+e, p]
//   Wc[512+f*H+h, p] = sum_e w2t[f,h,e] * wt[f*E+e, p]
// stored transposed + fp16 hi/lo:  g_Whi/g_Wlo [p][k]
// ============================================================================
__global__ void __launch_bounds__(128) precompute_kernel(
    const float* __restrict__ w2v, const float* __restrict__ w2t,
    const float* __restrict__ wx,  const float* __restrict__ wt) {
    int f  = blockIdx.y;
    int br = blockIdx.z;
    int p  = blockIdx.x * 128 + threadIdx.x;
    const float* w2 = br ? w2t : w2v;
    const float* w  = br ? wt  : wx;

    __shared__ float s_w2[H_DIM][E_DIM];
    for (int idx = threadIdx.x; idx < H_DIM * E_DIM; idx += 128)
        s_w2[idx >> 6][idx & 63] = w2[f * H_DIM * E_DIM + idx];
    __syncthreads();

    float acc[H_DIM];
#pragma unroll
    for (int h = 0; h < H_DIM; h++) acc[h] = 0.0f;

    const float* wcol = w + (size_t)f * E_DIM * P_DIM + p;
#pragma unroll 4
    for (int e = 0; e < E_DIM; e++) {
        float wv = wcol[(size_t)e * P_DIM];
#pragma unroll
        for (int h = 0; h < H_DIM; h++) acc[h] = fmaf(s_w2[h][e], wv, acc[h]);
    }

    int kb = br * 512 + f * 8;
    union { uint4 u; __half2 h2[4]; } Hv, Lv;
#pragma unroll
    for (int h2 = 0; h2 < 4; h2++) {
        __half h0, l0, h1, l1;
        split_h(acc[2 * h2 + 0], h0, l0);
        split_h(acc[2 * h2 + 1], h1, l1);
        Hv.h2[h2] = __halves2half2(h0, h1);
        Lv.h2[h2] = __halves2half2(l0, l1);
    }
    *reinterpret_cast<uint4*>(&g_Whi[(size_t)p * K_DIM + kb]) = Hv.u;
    *reinterpret_cast<uint4*>(&g_Wlo[(size_t)p * K_DIM + kb]) = Lv.u;
}

// ============================================================================
// Kernel 3: activations  H[i, f*8+h] = tanh(x[i,f]*w1[f,h] + b1[f,h])
//   fp16 hi/lo split into g_Hhi/g_Hlo [i][k]; one thread per (token,feature)
// ============================================================================
__global__ void __launch_bounds__(256) act_kernel(
    const float* __restrict__ x,   const float* __restrict__ tmv,
    const float* __restrict__ w1v, const float* __restrict__ b1v,
    const float* __restrict__ w1t, const float* __restrict__ b1t) {
    int idx = blockIdx.x * 256 + threadIdx.x;     // < BT_TOK * F_DIM
    int i = idx >> 6, f = idx & 63;
    float xv = x[idx], tv = tmv[idx];

    union { uint4 u; __half2 h2[4]; } XH, XL, TH, TL;
#pragma unroll
    for (int h2 = 0; h2 < 4; h2++) {
        int w0 = f * 8 + 2 * h2, w1 = w0 + 1;
        float a0 = tanhf(fmaf(xv, w1v[w0], b1v[w0]));
        float a1 = tanhf(fmaf(xv, w1v[w1], b1v[w1]));
        float c0 = tanhf(fmaf(tv, w1t[w0], b1t[w0]));
        float c1 = tanhf(fmaf(tv, w1t[w1], b1t[w1]));
        __half h0, l0, h1, l1;
        split_h(a0, h0, l0); split_h(a1, h1, l1);
        XH.h2[h2] = __halves2half2(h0, h1);
        XL.h2[h2] = __halves2half2(l0, l1);
        split_h(c0, h0, l0); split_h(c1, h1, l1);
        TH.h2[h2] = __halves2half2(h0, h1);
        TL.h2[h2] = __halves2half2(l0, l1);
    }
    size_t ox = (size_t)i * K_DIM + f * 8;
    size_t ot = ox + 512;
    *reinterpret_cast<uint4*>(&g_Hhi[ox]) = XH.u;
    *reinterpret_cast<uint4*>(&g_Hlo[ox]) = XL.u;
    *reinterpret_cast<uint4*>(&g_Hhi[ot]) = TH.u;
    *reinterpret_cast<uint4*>(&g_Hlo[ot]) = TL.u;
}

// ============================================================================
// Kernel 4: GEMM  out[16384,512] = H @ Wc^T + bias  via mma.sync (HMMA)
//   2-pass split precision: D = Ahi*Bhi + Alo*Bhi   (fp32 accum)
//   CTA 128x256, 512 threads, warp tile 32x64, Kc=64
//   3-stage cp.async ring, wait_group 1 (no per-iter drain)
// ============================================================================
#define CTA_M   128
#define CTA_N   256
#define KC      64
#define A_STAGE (CTA_M * KC * 2)            // 16 KB
#define B_STAGE (CTA_N * KC * 2)            // 32 KB
#define STAGE   (A_STAGE + B_STAGE)         // 48 KB
#define N_STAGES 3
#define SMEM_GEMM (N_STAGES * STAGE)        // 144 KB
#define N_ITERS 32                          // 2 passes * 16 K-chunks

__global__ void __launch_bounds__(512, 1) gemm_kernel(float* __restrict__ out) {
    extern __shared__ __align__(128) char smem[];
    const int tid  = threadIdx.x;
    const int lane = tid & 31;
    const int wid  = tid >> 5;
    const int wm   = (wid & 3) * 32;     // warp M offset in CTA tile
    const int wn   = (wid >> 2) * 64;    // warp N offset
    const int m0   = blockIdx.x * CTA_M;
    const int n0   = blockIdx.y * CTA_N;
    const uint32_t sb = smem_u32(smem);

    float acc[2][8][4];
#pragma unroll
    for (int im = 0; im < 2; im++)
#pragma unroll
        for (int in = 0; in < 8; in++)
#pragma unroll
            for (int q = 0; q < 4; q++) acc[im][in][q] = 0.0f;

    // ldmatrix per-lane row/col decomposition
    const int arow = (lane & 7) + ((lane >> 3) & 1) * 8;   // + wm + im*16
    const int acb  = (lane >> 4) & 1;                      // k+8 selector
    const int brow = (lane & 7) + ((lane >> 4) & 1) * 8;   // + wn + j*16
    const int bcb  = (lane >> 3) & 1;

    // stage loader: it -> (pass, kchunk); always commits a group
    auto load_stage = [&](int it, int stg) {
        if (it < N_ITERS) {
            int p  = it >> 4;                 // 0: Ahi, 1: Alo
            int kc = it & 15;
            const __half* A = p ? g_Hlo : g_Hhi;
            const __half* B = g_Whi;
            A += (size_t)m0 * K_DIM + kc * KC;
            B += (size_t)n0 * K_DIM + kc * KC;
            uint32_t base = sb + (uint32_t)stg * STAGE;
#pragma unroll
            for (int t = 0; t < 2; t++) {            // A: 1024 x 16B
                int u = tid + t * 512;
                int row = u >> 3, c = u & 7;
                uint32_t so = base + row * 128 + ((c ^ (row & 7)) << 4);
                cp_async16(so, (const char*)(A + (size_t)row * K_DIM) + c * 16);
            }
            uint32_t bb = base + A_STAGE;
#pragma unroll
            for (int t = 0; t < 4; t++) {            // B: 2048 x 16B
                int u = tid + t * 512;
                int row = u >> 3, c = u & 7;
                uint32_t so = bb + row * 128 + ((c ^ (row & 7)) << 4);
                cp_async16(so, (const char*)(B + (size_t)row * K_DIM) + c * 16);
            }
        }
        asm volatile("cp.async.commit_group;" ::: "memory");   // empty group OK past the end
    };

    load_stage(0, 0);
    load_stage(1, 1);

    int cs = 0;                           // compute stage = it % 3
    for (int it = 0; it < N_ITERS; it++) {
        // wait until <=1 group outstanding -> group for iter `it` complete
        asm volatile("cp.async.wait_group 1;" ::: "memory");
        __syncthreads();

        // issue loads for it+2 into stage (cs+2)%3 (consumed at iter it-1, safe after sync)
        int ls = cs + 2; if (ls >= N_STAGES) ls -= N_STAGES;
        load_stage(it + 2, ls);

        uint32_t abase = sb + (uint32_t)cs * STAGE;
        uint32_t bbase = abase + A_STAGE;
#pragma unroll
        for (int ks = 0; ks < 4; ks++) {
            uint32_t a[2][4];
#pragma unroll
            for (int im = 0; im < 2; im++) {
                int row = wm + arow + im * 16;
                int c = ks * 2 + acb;
                ldmatrix_x4(a[im], abase + row * 128 + ((c ^ (row & 7)) << 4));
            }
            uint32_t b[4][4];
#pragma unroll
            for (int j = 0; j < 4; j++) {
                int row = wn + brow + j * 16;
                int c = ks * 2 + bcb;
                ldmatrix_x4(b[j], bbase + row * 128 + ((c ^ (row & 7)) << 4));
            }
#pragma unroll
            for (int im = 0; im < 2; im++)
#pragma unroll
                for (int j = 0; j < 4; j++) {
                    mma16816(acc[im][2 * j],     a[im], b[j][0], b[j][1]);
                    mma16816(acc[im][2 * j + 1], a[im], b[j][2], b[j][3]);
                }
        }
        cs = cs + 1; if (cs >= N_STAGES) cs -= N_STAGES;
        // next iteration's __syncthreads (after its wait) protects stage reuse
        __syncthreads();
    }

    // epilogue: add bias, write fp32
#pragma unroll
    for (int im = 0; im < 2; im++) {
        int r0 = m0 + wm + im * 16 + (lane >> 2);
#pragma unroll
        for (int in = 0; in < 8; in++) {
            int cidx = n0 + wn + in * 8 + (lane & 3) * 2;
            float b0 = g_bias[cidx], b1 = g_bias[cidx + 1];
            float2 v0 = make_float2(acc[im][in][0] + b0, acc[im][in][1] + b1);
            float2 v1 = make_float2(acc[im][in][2] + b0, acc[im][in][3] + b1);
            *reinterpret_cast<float2*>(out + (size_t)r0 * P_DIM + cidx) = v0;
            *reinterpret_cast<float2*>(out + (size_t)(r0 + 8) * P_DIM + cidx) = v1;
        }
    }
}

// ============================================================================
extern "C" void kernel_launch(void* const* d_in, const int* in_sizes, int n_in,
                              void* d_out, int out_size) {
    const float* x   = (const float*)d_in[0];
    const float* tmv = (const float*)d_in[1];
    const float* w1v = (const float*)d_in[2];
    const float* b1v = (const float*)d_in[3];
    const float* w2v = (const float*)d_in[4];
    const float* w1t = (const float*)d_in[5];
    const float* b1t = (const float*)d_in[6];
    const float* w2t = (const float*)d_in[7];
    const float* wx  = (const float*)d_in[8];
    const float* bx  = (const float*)d_in[9];
    const float* wt  = (const float*)d_in[10];
    const float* bt  = (const float*)d_in[11];
    float* out = (float*)d_out;

    bias_kernel<<<1, 512>>>(bx, bt);
    precompute_kernel<<<dim3(4, 64, 2), 128>>>(w2v, w2t, wx, wt);
    act_kernel<<<(BT_TOK * F_DIM) / 256, 256>>>(x, tmv, w1v, b1v, w1t, b1t);

    cudaFuncSetAttribute(gemm_kernel, cudaFuncAttributeMaxDynamicSharedMemorySize, SMEM_GEMM);
    gemm_kernel<<<dim3(BT_TOK / CTA_M, P_DIM / CTA_N), 512, SMEM_GEMM>>>(out);
}

// round 12
// speedup vs baseline: 1.3520x; 1.0396x over previous
#include <cuda_runtime.h>
#include <cuda_fp16.h>
#include <cstdint>

// Problem dims
#define BT_TOK 16384   // B*T
#define F_DIM  64
#define H_DIM  8
#define E_DIM  64
#define P_DIM  512
#define K_DIM  1024    // 2 * F * H  (x-branch cols 0..511, time-branch 512..1023)

// -------- device scratch (static globals; no allocation allowed) --------
__device__ __half g_Hhi[(size_t)BT_TOK * K_DIM];
__device__ __half g_Hlo[(size_t)BT_TOK * K_DIM];
__device__ __half g_Whi[(size_t)P_DIM * K_DIM];   // [p][k]  K-contiguous (col-major B)
__device__ __half g_Wlo[(size_t)P_DIM * K_DIM];   // unused in 2-pass mode
__device__ float  g_bias[P_DIM];

// -------- helpers --------
__device__ __forceinline__ uint32_t smem_u32(const void* p) {
    uint32_t a;
    asm("{ .reg .u64 t; cvta.to.shared.u64 t, %1; cvt.u32.u64 %0, t; }" : "=r"(a) : "l"(p));
    return a;
}
__device__ __forceinline__ void cp_async16(uint32_t dst, const void* src) {
    asm volatile("cp.async.cg.shared.global [%0], [%1], 16;" :: "r"(dst), "l"(src));
}
__device__ __forceinline__ void ldmatrix_x4(uint32_t r[4], uint32_t addr) {
    asm volatile("ldmatrix.sync.aligned.m8n8.x4.shared.b16 {%0,%1,%2,%3}, [%4];"
                 : "=r"(r[0]), "=r"(r[1]), "=r"(r[2]), "=r"(r[3]) : "r"(addr));
}
__device__ __forceinline__ void mma16816(float c[4], const uint32_t a[4],
                                         uint32_t b0, uint32_t b1) {
    asm volatile(
        "mma.sync.aligned.m16n8k16.row.col.f32.f16.f16.f32 "
        "{%0,%1,%2,%3}, {%4,%5,%6,%7}, {%8,%9}, {%0,%1,%2,%3};"
        : "+f"(c[0]), "+f"(c[1]), "+f"(c[2]), "+f"(c[3])
        : "r"(a[0]), "r"(a[1]), "r"(a[2]), "r"(a[3]), "r"(b0), "r"(b1));
}
__device__ __forceinline__ void split_h(float v, __half& hi, __half& lo) {
    hi = __float2half_rn(v);
    lo = __float2half_rn(v - __half2float(hi));
}

// ============================================================================
// Kernel 1: bias fold
// ============================================================================
__global__ void bias_kernel(const float* __restrict__ bx, const float* __restrict__ bt) {
    int p = threadIdx.x;
    g_bias[p] = bx[p] + bt[p];
}

// ============================================================================
// Kernel 2: weight pre-contraction
//   Wc[f*H+h, p]     = sum_e w2v[f,h,e] * wx[f*E+e, p]
//   Wc[512+f*H+h, p] = sum_e w2t[f,h,e] * wt[f*E+e, p]
// stored transposed + fp16 hi/lo:  g_Whi/g_Wlo [p][k]
// ============================================================================
__global__ void __launch_bounds__(128) precompute_kernel(
    const float* __restrict__ w2v, const float* __restrict__ w2t,
    const float* __restrict__ wx,  const float* __restrict__ wt) {
    int f  = blockIdx.y;
    int br = blockIdx.z;
    int p  = blockIdx.x * 128 + threadIdx.x;
    const float* w2 = br ? w2t : w2v;
    const float* w  = br ? wt  : wx;

    __shared__ float s_w2[H_DIM][E_DIM];
    for (int idx = threadIdx.x; idx < H_DIM * E_DIM; idx += 128)
        s_w2[idx >> 6][idx & 63] = w2[f * H_DIM * E_DIM + idx];
    __syncthreads();

    float acc[H_DIM];
#pragma unroll
    for (int h = 0; h < H_DIM; h++) acc[h] = 0.0f;

    const float* wcol = w + (size_t)f * E_DIM * P_DIM + p;
#pragma unroll 4
    for (int e = 0; e < E_DIM; e++) {
        float wv = wcol[(size_t)e * P_DIM];
#pragma unroll
        for (int h = 0; h < H_DIM; h++) acc[h] = fmaf(s_w2[h][e], wv, acc[h]);
    }

    int kb = br * 512 + f * 8;
    union { uint4 u; __half2 h2[4]; } Hv, Lv;
#pragma unroll
    for (int h2 = 0; h2 < 4; h2++) {
        __half h0, l0, h1, l1;
        split_h(acc[2 * h2 + 0], h0, l0);
        split_h(acc[2 * h2 + 1], h1, l1);
        Hv.h2[h2] = __halves2half2(h0, h1);
        Lv.h2[h2] = __halves2half2(l0, l1);
    }
    *reinterpret_cast<uint4*>(&g_Whi[(size_t)p * K_DIM + kb]) = Hv.u;
    *reinterpret_cast<uint4*>(&g_Wlo[(size_t)p * K_DIM + kb]) = Lv.u;
}

// ============================================================================
// Kernel 3: activations  H[i, f*8+h] = tanh(x[i,f]*w1[f,h] + b1[f,h])
//   fp16 hi/lo split into g_Hhi/g_Hlo [i][k]; one thread per (token,feature)
// ============================================================================
__global__ void __launch_bounds__(256) act_kernel(
    const float* __restrict__ x,   const float* __restrict__ tmv,
    const float* __restrict__ w1v, const float* __restrict__ b1v,
    const float* __restrict__ w1t, const float* __restrict__ b1t) {
    int idx = blockIdx.x * 256 + threadIdx.x;     // < BT_TOK * F_DIM
    int i = idx >> 6, f = idx & 63;
    float xv = x[idx], tv = tmv[idx];

    union { uint4 u; __half2 h2[4]; } XH, XL, TH, TL;
#pragma unroll
    for (int h2 = 0; h2 < 4; h2++) {
        int w0 = f * 8 + 2 * h2, w1 = w0 + 1;
        float a0 = tanhf(fmaf(xv, w1v[w0], b1v[w0]));
        float a1 = tanhf(fmaf(xv, w1v[w1], b1v[w1]));
        float c0 = tanhf(fmaf(tv, w1t[w0], b1t[w0]));
        float c1 = tanhf(fmaf(tv, w1t[w1], b1t[w1]));
        __half h0, l0, h1, l1;
        split_h(a0, h0, l0); split_h(a1, h1, l1);
        XH.h2[h2] = __halves2half2(h0, h1);
        XL.h2[h2] = __halves2half2(l0, l1);
        split_h(c0, h0, l0); split_h(c1, h1, l1);
        TH.h2[h2] = __halves2half2(h0, h1);
        TL.h2[h2] = __halves2half2(l0, l1);
    }
    size_t ox = (size_t)i * K_DIM + f * 8;
    size_t ot = ox + 512;
    *reinterpret_cast<uint4*>(&g_Hhi[ox]) = XH.u;
    *reinterpret_cast<uint4*>(&g_Hlo[ox]) = XL.u;
    *reinterpret_cast<uint4*>(&g_Hhi[ot]) = TH.u;
    *reinterpret_cast<uint4*>(&g_Hlo[ot]) = TL.u;
}

// ============================================================================
// Kernel 4: GEMM  out[16384,512] = H @ Wc^T + bias  via mma.sync (HMMA)
//   interleaved 2-pass split precision per K-chunk:
//     acc += Ahi(kc)*B(kc); acc += Alo(kc)*B(kc)   (fp32 accum, B loaded once)
//   CTA 128x256, 512 threads, warp tile 32x64, Kc=64
//   3-stage cp.async ring {Ahi,Alo,B}, wait_group 1
// ============================================================================
#define CTA_M   128
#define CTA_N   256
#define KC      64
#define AH_OFF  0
#define AL_OFF  (CTA_M * KC * 2)            // 16 KB
#define B_OFF   (2 * CTA_M * KC * 2)        // 32 KB
#define STAGE   (B_OFF + CTA_N * KC * 2)    // 64 KB
#define N_STAGES 3
#define SMEM_GEMM (N_STAGES * STAGE)        // 192 KB
#define N_ITERS 16                          // 16 K-chunks, both passes fused

__global__ void __launch_bounds__(512, 1) gemm_kernel(float* __restrict__ out) {
    extern __shared__ __align__(128) char smem[];
    const int tid  = threadIdx.x;
    const int lane = tid & 31;
    const int wid  = tid >> 5;
    const int wm   = (wid & 3) * 32;     // warp M offset in CTA tile
    const int wn   = (wid >> 2) * 64;    // warp N offset
    const int m0   = blockIdx.x * CTA_M;
    const int n0   = blockIdx.y * CTA_N;
    const uint32_t sb = smem_u32(smem);

    float acc[2][8][4];
#pragma unroll
    for (int im = 0; im < 2; im++)
#pragma unroll
        for (int in = 0; in < 8; in++)
#pragma unroll
            for (int q = 0; q < 4; q++) acc[im][in][q] = 0.0f;

    // ldmatrix per-lane row/col decomposition
    const int arow = (lane & 7) + ((lane >> 3) & 1) * 8;   // + wm + im*16
    const int acb  = (lane >> 4) & 1;                      // k+8 selector
    const int brow = (lane & 7) + ((lane >> 4) & 1) * 8;   // + wn + j*16
    const int bcb  = (lane >> 3) & 1;

    // stage loader for K-chunk kc; always commits a group
    auto load_stage = [&](int kc, int stg) {
        if (kc < N_ITERS) {
            const __half* Ah = g_Hhi + (size_t)m0 * K_DIM + kc * KC;
            const __half* Al = g_Hlo + (size_t)m0 * K_DIM + kc * KC;
            const __half* B  = g_Whi + (size_t)n0 * K_DIM + kc * KC;
            uint32_t base = sb + (uint32_t)stg * STAGE;
#pragma unroll
            for (int t = 0; t < 2; t++) {            // Ahi: 1024 x 16B
                int u = tid + t * 512;
                int row = u >> 3, c = u & 7;
                uint32_t so = row * 128 + ((c ^ (row & 7)) << 4);
                cp_async16(base + AH_OFF + so, (const char*)(Ah + (size_t)row * K_DIM) + c * 16);
            }
#pragma unroll
            for (int t = 0; t < 2; t++) {            // Alo: 1024 x 16B
                int u = tid + t * 512;
                int row = u >> 3, c = u & 7;
                uint32_t so = row * 128 + ((c ^ (row & 7)) << 4);
                cp_async16(base + AL_OFF + so, (const char*)(Al + (size_t)row * K_DIM) + c * 16);
            }
#pragma unroll
            for (int t = 0; t < 4; t++) {            // B: 2048 x 16B
                int u = tid + t * 512;
                int row = u >> 3, c = u & 7;
                uint32_t so = row * 128 + ((c ^ (row & 7)) << 4);
                cp_async16(base + B_OFF + so, (const char*)(B + (size_t)row * K_DIM) + c * 16);
            }
        }
        asm volatile("cp.async.commit_group;" ::: "memory");   // empty group OK past the end
    };

    load_stage(0, 0);
    load_stage(1, 1);

    int cs = 0;                           // compute stage = kc % 3
    for (int kc = 0; kc < N_ITERS; kc++) {
        // wait until <=1 group outstanding -> group for chunk `kc` complete
        asm volatile("cp.async.wait_group 1;" ::: "memory");
        __syncthreads();      // also orders stage (cs+2)%3 reuse: its consumer was kc-1

        int ls = cs + 2; if (ls >= N_STAGES) ls -= N_STAGES;
        load_stage(kc + 2, ls);

        uint32_t base  = sb + (uint32_t)cs * STAGE;
        uint32_t bbase = base + B_OFF;
#pragma unroll
        for (int ks = 0; ks < 4; ks++) {
            uint32_t b[4][4];
#pragma unroll
            for (int j = 0; j < 4; j++) {
                int row = wn + brow + j * 16;
                int c = ks * 2 + bcb;
                ldmatrix_x4(b[j], bbase + row * 128 + ((c ^ (row & 7)) << 4));
            }
            uint32_t a[2][4];
            // hi pass
#pragma unroll
            for (int im = 0; im < 2; im++) {
                int row = wm + arow + im * 16;
                int c = ks * 2 + acb;
                ldmatrix_x4(a[im], base + AH_OFF + row * 128 + ((c ^ (row & 7)) << 4));
            }
#pragma unroll
            for (int im = 0; im < 2; im++)
#pragma unroll
                for (int j = 0; j < 4; j++) {
                    mma16816(acc[im][2 * j],     a[im], b[j][0], b[j][1]);
                    mma16816(acc[im][2 * j + 1], a[im], b[j][2], b[j][3]);
                }
            // lo pass (reuse a registers, B fragments)
#pragma unroll
            for (int im = 0; im < 2; im++) {
                int row = wm + arow + im * 16;
                int c = ks * 2 + acb;
                ldmatrix_x4(a[im], base + AL_OFF + row * 128 + ((c ^ (row & 7)) << 4));
            }
#pragma unroll
            for (int im = 0; im < 2; im++)
#pragma unroll
                for (int j = 0; j < 4; j++) {
                    mma16816(acc[im][2 * j],     a[im], b[j][0], b[j][1]);
                    mma16816(acc[im][2 * j + 1], a[im], b[j][2], b[j][3]);
                }
        }
        cs = cs + 1; if (cs >= N_STAGES) cs -= N_STAGES;
    }

    // epilogue: add bias, write fp32
#pragma unroll
    for (int im = 0; im < 2; im++) {
        int r0 = m0 + wm + im * 16 + (lane >> 2);
#pragma unroll
        for (int in = 0; in < 8; in++) {
            int cidx = n0 + wn + in * 8 + (lane & 3) * 2;
            float b0 = g_bias[cidx], b1 = g_bias[cidx + 1];
            float2 v0 = make_float2(acc[im][in][0] + b0, acc[im][in][1] + b1);
            float2 v1 = make_float2(acc[im][in][2] + b0, acc[im][in][3] + b1);
            *reinterpret_cast<float2*>(out + (size_t)r0 * P_DIM + cidx) = v0;
            *reinterpret_cast<float2*>(out + (size_t)(r0 + 8) * P_DIM + cidx) = v1;
        }
    }
}

// ============================================================================
extern "C" void kernel_launch(void* const* d_in, const int* in_sizes, int n_in,
                              void* d_out, int out_size) {
    const float* x   = (const float*)d_in[0];
    const float* tmv = (const float*)d_in[1];
    const float* w1v = (const float*)d_in[2];
    const float* b1v = (const float*)d_in[3];
    const float* w2v = (const float*)d_in[4];
    const float* w1t = (const float*)d_in[5];
    const float* b1t = (const float*)d_in[6];
    const float* w2t = (const float*)d_in[7];
    const float* wx  = (const float*)d_in[8];
    const float* bx  = (const float*)d_in[9];
    const float* wt  = (const float*)d_in[10];
    const float* bt  = (const float*)d_in[11];
    float* out = (float*)d_out;

    bias_kernel<<<1, 512>>>(bx, bt);
    precompute_kernel<<<dim3(4, 64, 2), 128>>>(w2v, w2t, wx, wt);
    act_kernel<<<(BT_TOK * F_DIM) / 256, 256>>>(x, tmv, w1v, b1v, w1t, b1t);

    cudaFuncSetAttribute(gemm_kernel, cudaFuncAttributeMaxDynamicSharedMemorySize, SMEM_GEMM);
    gemm_kernel<<<dim3(BT_TOK / CTA_M, P_DIM / CTA_N), 512, SMEM_GEMM>>>(out);
}

// round 14
// speedup vs baseline: 1.4253x; 1.0543x over previous
#include <cuda_runtime.h>
#include <cuda_fp16.h>
#include <cstdint>

// Problem dims
#define BT_TOK 16384   // B*T
#define F_DIM  64
#define H_DIM  8
#define E_DIM  64
#define P_DIM  512
#define K_DIM  1024    // 2 * F * H  (x-branch cols 0..511, time-branch 512..1023)

// -------- device scratch (static globals; no allocation allowed) --------
__device__ __half g_Hhi[(size_t)BT_TOK * K_DIM];
__device__ __half g_Hlo[(size_t)BT_TOK * K_DIM];
__device__ __half g_Whi[(size_t)P_DIM * K_DIM];   // [p][k]  K-contiguous (col-major B)
__device__ __half g_Wlo[(size_t)P_DIM * K_DIM];   // unused in 2-pass mode
__device__ float  g_bias[P_DIM];

// -------- helpers --------
__device__ __forceinline__ uint32_t smem_u32(const void* p) {
    uint32_t a;
    asm("{ .reg .u64 t; cvta.to.shared.u64 t, %1; cvt.u32.u64 %0, t; }" : "=r"(a) : "l"(p));
    return a;
}
__device__ __forceinline__ void cp_async16(uint32_t dst, const void* src) {
    asm volatile("cp.async.cg.shared.global [%0], [%1], 16;" :: "r"(dst), "l"(src));
}
__device__ __forceinline__ void ldmatrix_x4(uint32_t r[4], uint32_t addr) {
    asm volatile("ldmatrix.sync.aligned.m8n8.x4.shared.b16 {%0,%1,%2,%3}, [%4];"
                 : "=r"(r[0]), "=r"(r[1]), "=r"(r[2]), "=r"(r[3]) : "r"(addr));
}
__device__ __forceinline__ void mma16816(float c[4], const uint32_t a[4],
                                         uint32_t b0, uint32_t b1) {
    asm volatile(
        "mma.sync.aligned.m16n8k16.row.col.f32.f16.f16.f32 "
        "{%0,%1,%2,%3}, {%4,%5,%6,%7}, {%8,%9}, {%0,%1,%2,%3};"
        : "+f"(c[0]), "+f"(c[1]), "+f"(c[2]), "+f"(c[3])
        : "r"(a[0]), "r"(a[1]), "r"(a[2]), "r"(a[3]), "r"(b0), "r"(b1));
}
__device__ __forceinline__ void split_h(float v, __half& hi, __half& lo) {
    hi = __float2half_rn(v);
    lo = __float2half_rn(v - __half2float(hi));
}

// ============================================================================
// Kernel 1: bias fold
// ============================================================================
__global__ void bias_kernel(const float* __restrict__ bx, const float* __restrict__ bt) {
    int p = threadIdx.x;
    g_bias[p] = bx[p] + bt[p];
}

// ============================================================================
// Kernel 2: weight pre-contraction
//   Wc[f*H+h, p]     = sum_e w2v[f,h,e] * wx[f*E+e, p]
//   Wc[512+f*H+h, p] = sum_e w2t[f,h,e] * wt[f*E+e, p]
// stored transposed + fp16 hi/lo:  g_Whi/g_Wlo [p][k]
// ============================================================================
__global__ void __launch_bounds__(128) precompute_kernel(
    const float* __restrict__ w2v, const float* __restrict__ w2t,
    const float* __restrict__ wx,  const float* __restrict__ wt) {
    int f  = blockIdx.y;
    int br = blockIdx.z;
    int p  = blockIdx.x * 128 + threadIdx.x;
    const float* w2 = br ? w2t : w2v;
    const float* w  = br ? wt  : wx;

    __shared__ float s_w2[H_DIM][E_DIM];
    for (int idx = threadIdx.x; idx < H_DIM * E_DIM; idx += 128)
        s_w2[idx >> 6][idx & 63] = w2[f * H_DIM * E_DIM + idx];
    __syncthreads();

    float acc[H_DIM];
#pragma unroll
    for (int h = 0; h < H_DIM; h++) acc[h] = 0.0f;

    const float* wcol = w + (size_t)f * E_DIM * P_DIM + p;
#pragma unroll 4
    for (int e = 0; e < E_DIM; e++) {
        float wv = wcol[(size_t)e * P_DIM];
#pragma unroll
        for (int h = 0; h < H_DIM; h++) acc[h] = fmaf(s_w2[h][e], wv, acc[h]);
    }

    int kb = br * 512 + f * 8;
    union { uint4 u; __half2 h2[4]; } Hv, Lv;
#pragma unroll
    for (int h2 = 0; h2 < 4; h2++) {
        __half h0, l0, h1, l1;
        split_h(acc[2 * h2 + 0], h0, l0);
        split_h(acc[2 * h2 + 1], h1, l1);
        Hv.h2[h2] = __halves2half2(h0, h1);
        Lv.h2[h2] = __halves2half2(l0, l1);
    }
    *reinterpret_cast<uint4*>(&g_Whi[(size_t)p * K_DIM + kb]) = Hv.u;
    *reinterpret_cast<uint4*>(&g_Wlo[(size_t)p * K_DIM + kb]) = Lv.u;
}

// ============================================================================
// Kernel 3: activations  H[i, f*8+h] = tanh(x[i,f]*w1[f,h] + b1[f,h])
//   fp16 hi/lo split into g_Hhi/g_Hlo [i][k]; one thread per (token,feature)
// ============================================================================
__global__ void __launch_bounds__(256) act_kernel(
    const float* __restrict__ x,   const float* __restrict__ tmv,
    const float* __restrict__ w1v, const float* __restrict__ b1v,
    const float* __restrict__ w1t, const float* __restrict__ b1t) {
    int idx = blockIdx.x * 256 + threadIdx.x;     // < BT_TOK * F_DIM
    int i = idx >> 6, f = idx & 63;
    float xv = x[idx], tv = tmv[idx];

    union { uint4 u; __half2 h2[4]; } XH, XL, TH, TL;
#pragma unroll
    for (int h2 = 0; h2 < 4; h2++) {
        int w0 = f * 8 + 2 * h2, w1 = w0 + 1;
        float a0 = tanhf(fmaf(xv, w1v[w0], b1v[w0]));
        float a1 = tanhf(fmaf(xv, w1v[w1], b1v[w1]));
        float c0 = tanhf(fmaf(tv, w1t[w0], b1t[w0]));
        float c1 = tanhf(fmaf(tv, w1t[w1], b1t[w1]));
        __half h0, l0, h1, l1;
        split_h(a0, h0, l0); split_h(a1, h1, l1);
        XH.h2[h2] = __halves2half2(h0, h1);
        XL.h2[h2] = __halves2half2(l0, l1);
        split_h(c0, h0, l0); split_h(c1, h1, l1);
        TH.h2[h2] = __halves2half2(h0, h1);
        TL.h2[h2] = __halves2half2(l0, l1);
    }
    size_t ox = (size_t)i * K_DIM + f * 8;
    size_t ot = ox + 512;
    *reinterpret_cast<uint4*>(&g_Hhi[ox]) = XH.u;
    *reinterpret_cast<uint4*>(&g_Hlo[ox]) = XL.u;
    *reinterpret_cast<uint4*>(&g_Hhi[ot]) = TH.u;
    *reinterpret_cast<uint4*>(&g_Hlo[ot]) = TL.u;
}

// ============================================================================
// Kernel 4: GEMM  out[16384,512] = H @ Wc^T + bias  via mma.sync (HMMA)
//   interleaved 2-pass split precision per K-chunk:
//     acc += Ahi(kc)*B(kc); acc += Alo(kc)*B(kc)   (fp32 accum, B loaded once)
//   CTA 128x128, 256 threads (8 warps, 4x2), warp tile 32x64, Kc=64
//   2-stage cp.async double buffer, wait_group 1, 2 CTAs/SM
// ============================================================================
#define CTA_M   128
#define CTA_N   128
#define KC      64
#define AH_OFF  0
#define AL_OFF  (CTA_M * KC * 2)            // 16 KB
#define B_OFF   (2 * CTA_M * KC * 2)        // 32 KB
#define STAGE   (B_OFF + CTA_N * KC * 2)    // 48 KB
#define N_STAGES 2
#define SMEM_GEMM (N_STAGES * STAGE)        // 96 KB -> 2 CTAs/SM
#define N_ITERS 16                          // 16 K-chunks, both passes fused

__global__ void __launch_bounds__(256, 2) gemm_kernel(float* __restrict__ out) {
    extern __shared__ __align__(128) char smem[];
    const int tid  = threadIdx.x;
    const int lane = tid & 31;
    const int wid  = tid >> 5;
    const int wm   = (wid & 3) * 32;     // warp M offset in CTA tile
    const int wn   = (wid >> 2) * 64;    // warp N offset
    const int m0   = blockIdx.x * CTA_M;
    const int n0   = blockIdx.y * CTA_N;
    const uint32_t sb = smem_u32(smem);

    float acc[2][8][4];
#pragma unroll
    for (int im = 0; im < 2; im++)
#pragma unroll
        for (int in = 0; in < 8; in++)
#pragma unroll
            for (int q = 0; q < 4; q++) acc[im][in][q] = 0.0f;

    // ldmatrix per-lane row/col decomposition
    const int arow = (lane & 7) + ((lane >> 3) & 1) * 8;   // + wm + im*16
    const int acb  = (lane >> 4) & 1;                      // k+8 selector
    const int brow = (lane & 7) + ((lane >> 4) & 1) * 8;   // + wn + j*16
    const int bcb  = (lane >> 3) & 1;

    // stage loader for K-chunk kc; always commits a group
    auto load_stage = [&](int kc, int stg) {
        if (kc < N_ITERS) {
            const __half* Ah = g_Hhi + (size_t)m0 * K_DIM + kc * KC;
            const __half* Al = g_Hlo + (size_t)m0 * K_DIM + kc * KC;
            const __half* B  = g_Whi + (size_t)n0 * K_DIM + kc * KC;
            uint32_t base = sb + (uint32_t)stg * STAGE;
#pragma unroll
            for (int t = 0; t < 4; t++) {            // Ahi: 1024 x 16B
                int u = tid + t * 256;
                int row = u >> 3, c = u & 7;
                uint32_t so = row * 128 + ((c ^ (row & 7)) << 4);
                cp_async16(base + AH_OFF + so, (const char*)(Ah + (size_t)row * K_DIM) + c * 16);
            }
#pragma unroll
            for (int t = 0; t < 4; t++) {            // Alo: 1024 x 16B
                int u = tid + t * 256;
                int row = u >> 3, c = u & 7;
                uint32_t so = row * 128 + ((c ^ (row & 7)) << 4);
                cp_async16(base + AL_OFF + so, (const char*)(Al + (size_t)row * K_DIM) + c * 16);
            }
#pragma unroll
            for (int t = 0; t < 4; t++) {            // B: 1024 x 16B
                int u = tid + t * 256;
                int row = u >> 3, c = u & 7;
                uint32_t so = row * 128 + ((c ^ (row & 7)) << 4);
                cp_async16(base + B_OFF + so, (const char*)(B + (size_t)row * K_DIM) + c * 16);
            }
        }
        asm volatile("cp.async.commit_group;" ::: "memory");   // empty group OK past the end
    };

    load_stage(0, 0);
    load_stage(1, 1);

    for (int kc = 0; kc < N_ITERS; kc++) {
        const int cs = kc & 1;
        // wait until <=1 group outstanding -> group for chunk `kc` complete
        asm volatile("cp.async.wait_group 1;" ::: "memory");
        __syncthreads();

        uint32_t base  = sb + (uint32_t)cs * STAGE;
        uint32_t bbase = base + B_OFF;
#pragma unroll
        for (int ks = 0; ks < 4; ks++) {
            uint32_t b[4][4];
#pragma unroll
            for (int j = 0; j < 4; j++) {
                int row = wn + brow + j * 16;
                int c = ks * 2 + bcb;
                ldmatrix_x4(b[j], bbase + row * 128 + ((c ^ (row & 7)) << 4));
            }
            uint32_t a[2][4];
            // hi pass
#pragma unroll
            for (int im = 0; im < 2; im++) {
                int row = wm + arow + im * 16;
                int c = ks * 2 + acb;
                ldmatrix_x4(a[im], base + AH_OFF + row * 128 + ((c ^ (row & 7)) << 4));
            }
#pragma unroll
            for (int im = 0; im < 2; im++)
#pragma unroll
                for (int j = 0; j < 4; j++) {
                    mma16816(acc[im][2 * j],     a[im], b[j][0], b[j][1]);
                    mma16816(acc[im][2 * j + 1], a[im], b[j][2], b[j][3]);
                }
            // lo pass (reuse a registers, B fragments)
#pragma unroll
            for (int im = 0; im < 2; im++) {
                int row = wm + arow + im * 16;
                int c = ks * 2 + acb;
                ldmatrix_x4(a[im], base + AL_OFF + row * 128 + ((c ^ (row & 7)) << 4));
            }
#pragma unroll
            for (int im = 0; im < 2; im++)
#pragma unroll
                for (int j = 0; j < 4; j++) {
                    mma16816(acc[im][2 * j],     a[im], b[j][0], b[j][1]);
                    mma16816(acc[im][2 * j + 1], a[im], b[j][2], b[j][3]);
                }
        }
        __syncthreads();           // compute(kc) done before overwriting its stage
        load_stage(kc + 2, cs);    // refill the stage just consumed
    }

    // epilogue: add bias, write fp32
#pragma unroll
    for (int im = 0; im < 2; im++) {
        int r0 = m0 + wm + im * 16 + (lane >> 2);
#pragma unroll
        for (int in = 0; in < 8; in++) {
            int cidx = n0 + wn + in * 8 + (lane & 3) * 2;
            float b0 = g_bias[cidx], b1 = g_bias[cidx + 1];
            float2 v0 = make_float2(acc[im][in][0] + b0, acc[im][in][1] + b1);
            float2 v1 = make_float2(acc[im][in][2] + b0, acc[im][in][3] + b1);
            *reinterpret_cast<float2*>(out + (size_t)r0 * P_DIM + cidx) = v0;
            *reinterpret_cast<float2*>(out + (size_t)(r0 + 8) * P_DIM + cidx) = v1;
        }
    }
}

// ============================================================================
extern "C" void kernel_launch(void* const* d_in, const int* in_sizes, int n_in,
                              void* d_out, int out_size) {
    const float* x   = (const float*)d_in[0];
    const float* tmv = (const float*)d_in[1];
    const float* w1v = (const float*)d_in[2];
    const float* b1v = (const float*)d_in[3];
    const float* w2v = (const float*)d_in[4];
    const float* w1t = (const float*)d_in[5];
    const float* b1t = (const float*)d_in[6];
    const float* w2t = (const float*)d_in[7];
    const float* wx  = (const float*)d_in[8];
    const float* bx  = (const float*)d_in[9];
    const float* wt  = (const float*)d_in[10];
    const float* bt  = (const float*)d_in[11];
    float* out = (float*)d_out;

    bias_kernel<<<1, 512>>>(bx, bt);
    precompute_kernel<<<dim3(4, 64, 2), 128>>>(w2v, w2t, wx, wt);
    act_kernel<<<(BT_TOK * F_DIM) / 256, 256>>>(x, tmv, w1v, b1v, w1t, b1t);

    cudaFuncSetAttribute(gemm_kernel, cudaFuncAttributeMaxDynamicSharedMemorySize, SMEM_GEMM);
    gemm_kernel<<<dim3(BT_TOK / CTA_M, P_DIM / CTA_N), 256, SMEM_GEMM>>>(out);
}

// round 16
// speedup vs baseline: 1.9499x; 1.3680x over previous
#include <cuda_runtime.h>
#include <cuda_fp16.h>
#include <cstdint>

// Problem dims
#define BT_TOK 16384   // B*T
#define F_DIM  64
#define H_DIM  8
#define E_DIM  64
#define P_DIM  512
#define K_DIM  1024    // 2 * F * H  (x-branch cols 0..511, time-branch 512..1023)

// -------- device scratch (static globals; no allocation allowed) --------
__device__ __half g_H[(size_t)BT_TOK * K_DIM];    // fp16 activations
__device__ __half g_W[(size_t)P_DIM * K_DIM];     // [p][k] K-contiguous (col-major B)
__device__ float  g_bias[P_DIM];

// -------- helpers --------
__device__ __forceinline__ uint32_t smem_u32(const void* p) {
    uint32_t a;
    asm("{ .reg .u64 t; cvta.to.shared.u64 t, %1; cvt.u32.u64 %0, t; }" : "=r"(a) : "l"(p));
    return a;
}
__device__ __forceinline__ void cp_async16(uint32_t dst, const void* src) {
    asm volatile("cp.async.cg.shared.global [%0], [%1], 16;" :: "r"(dst), "l"(src));
}
__device__ __forceinline__ void ldmatrix_x4(uint32_t r[4], uint32_t addr) {
    asm volatile("ldmatrix.sync.aligned.m8n8.x4.shared.b16 {%0,%1,%2,%3}, [%4];"
                 : "=r"(r[0]), "=r"(r[1]), "=r"(r[2]), "=r"(r[3]) : "r"(addr));
}
__device__ __forceinline__ void mma16816(float c[4], const uint32_t a[4],
                                         uint32_t b0, uint32_t b1) {
    asm volatile(
        "mma.sync.aligned.m16n8k16.row.col.f32.f16.f16.f32 "
        "{%0,%1,%2,%3}, {%4,%5,%6,%7}, {%8,%9}, {%0,%1,%2,%3};"
        : "+f"(c[0]), "+f"(c[1]), "+f"(c[2]), "+f"(c[3])
        : "r"(a[0]), "r"(a[1]), "r"(a[2]), "r"(a[3]), "r"(b0), "r"(b1));
}

// ============================================================================
// Kernel 1: bias fold
// ============================================================================
__global__ void bias_kernel(const float* __restrict__ bx, const float* __restrict__ bt) {
    int p = threadIdx.x;
    g_bias[p] = bx[p] + bt[p];
}

// ============================================================================
// Kernel 2: weight pre-contraction
//   Wc[f*H+h, p]     = sum_e w2v[f,h,e] * wx[f*E+e, p]
//   Wc[512+f*H+h, p] = sum_e w2t[f,h,e] * wt[f*E+e, p]
// stored transposed fp16:  g_W [p][k]
// ============================================================================
__global__ void __launch_bounds__(128) precompute_kernel(
    const float* __restrict__ w2v, const float* __restrict__ w2t,
    const float* __restrict__ wx,  const float* __restrict__ wt) {
    int f  = blockIdx.y;
    int br = blockIdx.z;
    int p  = blockIdx.x * 128 + threadIdx.x;
    const float* w2 = br ? w2t : w2v;
    const float* w  = br ? wt  : wx;

    __shared__ float s_w2[H_DIM][E_DIM];
    for (int idx = threadIdx.x; idx < H_DIM * E_DIM; idx += 128)
        s_w2[idx >> 6][idx & 63] = w2[f * H_DIM * E_DIM + idx];
    __syncthreads();

    float acc[H_DIM];
#pragma unroll
    for (int h = 0; h < H_DIM; h++) acc[h] = 0.0f;

    const float* wcol = w + (size_t)f * E_DIM * P_DIM + p;
#pragma unroll 4
    for (int e = 0; e < E_DIM; e++) {
        float wv = wcol[(size_t)e * P_DIM];
#pragma unroll
        for (int h = 0; h < H_DIM; h++) acc[h] = fmaf(s_w2[h][e], wv, acc[h]);
    }

    int kb = br * 512 + f * 8;
    union { uint4 u; __half2 h2[4]; } Hv;
#pragma unroll
    for (int h2 = 0; h2 < 4; h2++)
        Hv.h2[h2] = __halves2half2(__float2half_rn(acc[2 * h2]),
                                   __float2half_rn(acc[2 * h2 + 1]));
    *reinterpret_cast<uint4*>(&g_W[(size_t)p * K_DIM + kb]) = Hv.u;
}

// ============================================================================
// Kernel 3: activations  H[i, f*8+h] = tanh(x[i,f]*w1[f,h] + b1[f,h])
//   fp16, one thread per (token,feature), both branches
// ============================================================================
__global__ void __launch_bounds__(256) act_kernel(
    const float* __restrict__ x,   const float* __restrict__ tmv,
    const float* __restrict__ w1v, const float* __restrict__ b1v,
    const float* __restrict__ w1t, const float* __restrict__ b1t) {
    int idx = blockIdx.x * 256 + threadIdx.x;     // < BT_TOK * F_DIM
    int i = idx >> 6, f = idx & 63;
    float xv = x[idx], tv = tmv[idx];

    union { uint4 u; __half2 h2[4]; } XH, TH;
#pragma unroll
    for (int h2 = 0; h2 < 4; h2++) {
        int w0 = f * 8 + 2 * h2, w1 = w0 + 1;
        float a0 = tanhf(fmaf(xv, w1v[w0], b1v[w0]));
        float a1 = tanhf(fmaf(xv, w1v[w1], b1v[w1]));
        float c0 = tanhf(fmaf(tv, w1t[w0], b1t[w0]));
        float c1 = tanhf(fmaf(tv, w1t[w1], b1t[w1]));
        XH.h2[h2] = __halves2half2(__float2half_rn(a0), __float2half_rn(a1));
        TH.h2[h2] = __halves2half2(__float2half_rn(c0), __float2half_rn(c1));
    }
    size_t ox = (size_t)i * K_DIM + f * 8;
    *reinterpret_cast<uint4*>(&g_H[ox])       = XH.u;
    *reinterpret_cast<uint4*>(&g_H[ox + 512]) = TH.u;
}

// ============================================================================
// Kernel 4: GEMM  out[16384,512] = H @ Wc^T + bias  via mma.sync (HMMA)
//   single-pass fp16 (fp32 accum)
//   CTA 128x128, 256 threads (8 warps, 4x2), warp tile 32x64, Kc=64
//   3-stage cp.async ring, wait_group 2, 2 CTAs/SM
// ============================================================================
#define CTA_M   128
#define CTA_N   128
#define KC      64
#define A_OFF   0
#define B_OFF   (CTA_M * KC * 2)            // 16 KB
#define STAGE   (B_OFF + CTA_N * KC * 2)    // 32 KB
#define N_STAGES 3
#define SMEM_GEMM (N_STAGES * STAGE)        // 96 KB -> 2 CTAs/SM
#define N_ITERS 16                          // 16 K-chunks

__global__ void __launch_bounds__(256, 2) gemm_kernel(float* __restrict__ out) {
    extern __shared__ __align__(128) char smem[];
    const int tid  = threadIdx.x;
    const int lane = tid & 31;
    const int wid  = tid >> 5;
    const int wm   = (wid & 3) * 32;     // warp M offset in CTA tile
    const int wn   = (wid >> 2) * 64;    // warp N offset
    const int m0   = blockIdx.x * CTA_M;
    const int n0   = blockIdx.y * CTA_N;
    const uint32_t sb = smem_u32(smem);

    float acc[2][8][4];
#pragma unroll
    for (int im = 0; im < 2; im++)
#pragma unroll
        for (int in = 0; in < 8; in++)
#pragma unroll
            for (int q = 0; q < 4; q++) acc[im][in][q] = 0.0f;

    // ldmatrix per-lane row/col decomposition
    const int arow = (lane & 7) + ((lane >> 3) & 1) * 8;   // + wm + im*16
    const int acb  = (lane >> 4) & 1;                      // k+8 selector
    const int brow = (lane & 7) + ((lane >> 4) & 1) * 8;   // + wn + j*16
    const int bcb  = (lane >> 3) & 1;

    // stage loader for K-chunk kc; always commits a group
    auto load_stage = [&](int kc, int stg) {
        if (kc < N_ITERS) {
            const __half* A = g_H + (size_t)m0 * K_DIM + kc * KC;
            const __half* B = g_W + (size_t)n0 * K_DIM + kc * KC;
            uint32_t base = sb + (uint32_t)stg * STAGE;
#pragma unroll
            for (int t = 0; t < 4; t++) {            // A: 1024 x 16B
                int u = tid + t * 256;
                int row = u >> 3, c = u & 7;
                uint32_t so = row * 128 + ((c ^ (row & 7)) << 4);
                cp_async16(base + A_OFF + so, (const char*)(A + (size_t)row * K_DIM) + c * 16);
            }
#pragma unroll
            for (int t = 0; t < 4; t++) {            // B: 1024 x 16B
                int u = tid + t * 256;
                int row = u >> 3, c = u & 7;
                uint32_t so = row * 128 + ((c ^ (row & 7)) << 4);
                cp_async16(base + B_OFF + so, (const char*)(B + (size_t)row * K_DIM) + c * 16);
            }
        }
        asm volatile("cp.async.commit_group;" ::: "memory");   // empty group OK past the end
    };

    load_stage(0, 0);
    load_stage(1, 1);
    load_stage(2, 2);

    int cs = 0;                           // compute stage = kc % 3
    for (int kc = 0; kc < N_ITERS; kc++) {
        // wait until <=2 groups outstanding -> group for chunk `kc` complete
        asm volatile("cp.async.wait_group 2;" ::: "memory");
        __syncthreads();

        uint32_t base  = sb + (uint32_t)cs * STAGE;
        uint32_t bbase = base + B_OFF;
#pragma unroll
        for (int ks = 0; ks < 4; ks++) {
            uint32_t b[4][4];
#pragma unroll
            for (int j = 0; j < 4; j++) {
                int row = wn + brow + j * 16;
                int c = ks * 2 + bcb;
                ldmatrix_x4(b[j], bbase + row * 128 + ((c ^ (row & 7)) << 4));
            }
            uint32_t a[2][4];
#pragma unroll
            for (int im = 0; im < 2; im++) {
                int row = wm + arow + im * 16;
                int c = ks * 2 + acb;
                ldmatrix_x4(a[im], base + A_OFF + row * 128 + ((c ^ (row & 7)) << 4));
            }
#pragma unroll
            for (int im = 0; im < 2; im++)
#pragma unroll
                for (int j = 0; j < 4; j++) {
                    mma16816(acc[im][2 * j],     a[im], b[j][0], b[j][1]);
                    mma16816(acc[im][2 * j + 1], a[im], b[j][2], b[j][3]);
                }
        }
        __syncthreads();           // compute(kc) done before overwriting its stage
        load_stage(kc + 3, cs);    // refill the stage just consumed
        cs = cs + 1; if (cs >= N_STAGES) cs -= N_STAGES;
    }

    // epilogue: add bias, write fp32
#pragma unroll
    for (int im = 0; im < 2; im++) {
        int r0 = m0 + wm + im * 16 + (lane >> 2);
#pragma unroll
        for (int in = 0; in < 8; in++) {
            int cidx = n0 + wn + in * 8 + (lane & 3) * 2;
            float b0 = g_bias[cidx], b1 = g_bias[cidx + 1];
            float2 v0 = make_float2(acc[im][in][0] + b0, acc[im][in][1] + b1);
            float2 v1 = make_float2(acc[im][in][2] + b0, acc[im][in][3] + b1);
            *reinterpret_cast<float2*>(out + (size_t)r0 * P_DIM + cidx) = v0;
            *reinterpret_cast<float2*>(out + (size_t)(r0 + 8) * P_DIM + cidx) = v1;
        }
    }
}

// ============================================================================
extern "C" void kernel_launch(void* const* d_in, const int* in_sizes, int n_in,
                              void* d_out, int out_size) {
    const float* x   = (const float*)d_in[0];
    const float* tmv = (const float*)d_in[1];
    const float* w1v = (const float*)d_in[2];
    const float* b1v = (const float*)d_in[3];
    const float* w2v = (const float*)d_in[4];
    const float* w1t = (const float*)d_in[5];
    const float* b1t = (const float*)d_in[6];
    const float* w2t = (const float*)d_in[7];
    const float* wx  = (const float*)d_in[8];
    const float* bx  = (const float*)d_in[9];
    const float* wt  = (const float*)d_in[10];
    const float* bt  = (const float*)d_in[11];
    float* out = (float*)d_out;

    bias_kernel<<<1, 512>>>(bx, bt);
    precompute_kernel<<<dim3(4, 64, 2), 128>>>(w2v, w2t, wx, wt);
    act_kernel<<<(BT_TOK * F_DIM) / 256, 256>>>(x, tmv, w1v, b1v, w1t, b1t);

    cudaFuncSetAttribute(gemm_kernel, cudaFuncAttributeMaxDynamicSharedMemorySize, SMEM_GEMM);
    gemm_kernel<<<dim3(BT_TOK / CTA_M, P_DIM / CTA_N), 256, SMEM_GEMM>>>(out);
}